// round 5
// baseline (speedup 1.0000x reference)
#include <cuda_runtime.h>
#include <cuda_bf16.h>
#include <cstdint>

// ---------------- problem constants ----------------
#define CIN 128
#define COUT 256
#define NPIX (8 * 128 * 128)               // input pixels = 131072
#define M_TOTAL 32768                      // 8 * 64 * 64
#define K_TOTAL 1152                       // 9 * 128
#define FEATS_OUT_ELEMS ((size_t)M_TOTAL * COUT)
#define COORD_OUT_ELEMS ((size_t)M_TOTAL * 3)

// ---------------- GEMM config ----------------
#define BM 128
#define BN 128
#define BK 32                 // bf16 k per chunk
#define NCHUNK 36             // K_TOTAL / BK
#define NTHREADS 256

// smem stage layout, 80B row stride (conflict-free permutation for ldmatrix):
//   +0      Ahi [128][40] bf16 (10240 B)
//   +10240  Alo
//   +20480  Bhi [128][40]  (B stored [n][k])
//   +30720  Blo
#define LDS_STRIDE_B 80
#define OFF_ALO 10240
#define OFF_BHI 20480
#define OFF_BLO 30720
#define STAGE_BYTES 40960
#define SMEM_TOTAL (2 * STAGE_BYTES)   // 81920; 2 CTAs/SM -> 160KB/SM

// ---------------- device scratch ----------------
// weights transposed + split: [n][k] bf16
__device__ __align__(16) __nv_bfloat16 g_Whi[COUT * K_TOTAL];
__device__ __align__(16) __nv_bfloat16 g_Wlo[COUT * K_TOTAL];
// feats split: [pixel][c] bf16 (33.5 MB each)
__device__ __align__(16) __nv_bfloat16 g_Ahi[(size_t)NPIX * CIN];
__device__ __align__(16) __nv_bfloat16 g_Alo[(size_t)NPIX * CIN];

// ---------------- helpers ----------------
__device__ __forceinline__ uint32_t smem_u32(const void* p) {
    uint32_t a;
    asm("{ .reg .u64 t; cvta.to.shared.u64 t, %1; cvt.u32.u64 %0, t; }" : "=r"(a) : "l"(p));
    return a;
}
__device__ __forceinline__ void cp_async16(uint32_t dst, const void* src) {
    asm volatile("cp.async.cg.shared.global [%0], [%1], 16;" :: "r"(dst), "l"(src) : "memory");
}
// zero-fills when src_size == 0 (halo taps)
__device__ __forceinline__ void cp_async16z(uint32_t dst, const void* src, uint32_t src_size) {
    asm volatile("cp.async.cg.shared.global [%0], [%1], 16, %2;"
                 :: "r"(dst), "l"(src), "r"(src_size) : "memory");
}
__device__ __forceinline__ void cp_commit() {
    asm volatile("cp.async.commit_group;" ::: "memory");
}
__device__ __forceinline__ void cp_wait_all() {
    asm volatile("cp.async.wait_group 0;" ::: "memory");
}
__device__ __forceinline__ void ldsm_x4(uint32_t& r0, uint32_t& r1, uint32_t& r2, uint32_t& r3,
                                        uint32_t addr) {
    asm volatile("ldmatrix.sync.aligned.m8n8.x4.shared.b16 {%0,%1,%2,%3}, [%4];"
                 : "=r"(r0), "=r"(r1), "=r"(r2), "=r"(r3) : "r"(addr));
}
__device__ __forceinline__ void mma16816(float* c, const uint32_t* a, uint32_t b0, uint32_t b1) {
    asm volatile("mma.sync.aligned.m16n8k16.row.col.f32.bf16.bf16.f32 "
                 "{%0,%1,%2,%3}, {%4,%5,%6,%7}, {%8,%9}, {%0,%1,%2,%3};"
                 : "+f"(c[0]), "+f"(c[1]), "+f"(c[2]), "+f"(c[3])
                 : "r"(a[0]), "r"(a[1]), "r"(a[2]), "r"(a[3]), "r"(b0), "r"(b1));
}

// ---------------- weight split/transpose ----------------
__global__ void wconv_kernel(const float* __restrict__ w) {
    int idx = blockIdx.x * 256 + threadIdx.x;
    if (idx < K_TOTAL * COUT) {
        int k = idx >> 8;
        int n = idx & 255;
        float x = w[idx];
        __nv_bfloat16 h = __float2bfloat16(x);
        g_Whi[n * K_TOTAL + k] = h;
        g_Wlo[n * K_TOTAL + k] = __float2bfloat16(x - __bfloat162float(h));
    }
}

// ---------------- feats split (streaming, bandwidth-bound) ----------------
__global__ __launch_bounds__(256)
void asplit_kernel(const float* __restrict__ feats) {
    size_t i4 = (size_t)blockIdx.x * 256 + threadIdx.x;   // one float4 per thread
    const size_t total4 = (size_t)NPIX * CIN / 4;
    if (i4 < total4) {
        float4 v = reinterpret_cast<const float4*>(feats)[i4];
        __nv_bfloat162 h0 = __floats2bfloat162_rn(v.x, v.y);
        __nv_bfloat162 h1 = __floats2bfloat162_rn(v.z, v.w);
        __nv_bfloat162 l0 = __floats2bfloat162_rn(v.x - __bfloat162float(h0.x),
                                                  v.y - __bfloat162float(h0.y));
        __nv_bfloat162 l1 = __floats2bfloat162_rn(v.z - __bfloat162float(h1.x),
                                                  v.w - __bfloat162float(h1.y));
        uint2 hp = make_uint2(*reinterpret_cast<uint32_t*>(&h0),
                              *reinterpret_cast<uint32_t*>(&h1));
        uint2 lp = make_uint2(*reinterpret_cast<uint32_t*>(&l0),
                              *reinterpret_cast<uint32_t*>(&l1));
        reinterpret_cast<uint2*>(g_Ahi)[i4] = hp;
        reinterpret_cast<uint2*>(g_Alo)[i4] = lp;
    }
}

// ---------------- main GEMM kernel ----------------
__global__ __launch_bounds__(NTHREADS, 2)
void conv_mma_kernel(const float* __restrict__ alpha,
                     float* __restrict__ out)
{
    extern __shared__ char smem[];
    const uint32_t sb = smem_u32(smem);
    const int tid = threadIdx.x;
    const int w = tid >> 5, l = tid & 31;
    const int mblk = blockIdx.x, nblk = blockIdx.y;
    const int wm = w & 3, wn = w >> 2;      // 4 m-warps x 2 n-warps, warp tile 32x64

    // coords + alpha tail (once, from the nblk==0 plane)
    if (nblk == 0) {
        if (tid < 128) {
            int p = mblk * 128 + tid;
            float* row = out + FEATS_OUT_ELEMS + (size_t)p * 3;
            row[0] = (float)(p >> 12);
            row[1] = (float)((p & 4095) >> 6);
            row[2] = (float)(p & 63);
        }
        if (mblk == 0 && tid == 128)
            out[FEATS_OUT_ELEMS + COORD_OUT_ELEMS] = alpha[0];
    }

    // ---- loader geometry: thread t -> row (0..127), 32B segment (0/1)
    const int lrow = tid >> 1;
    const int lseg = tid & 1;               // 16 bf16 = 32B per seg
    // A side: output pixel
    const int p   = mblk * 128 + lrow;
    const int ab  = p >> 12;
    const int aoy = ((p & 4095) >> 6) << 1;
    const int aox = (p & 63) << 1;
    // B side
    const int bgn = nblk * 128 + lrow;

    // per-chunk cp.async issue for chunk cc into stage stg
    auto issue_chunk = [&](int cc, int stg) {
        const int tap = cc >> 2, kc = (cc & 3) << 5;
        const int iy = aoy + tap / 3 - 1;
        const int ix = aox + tap % 3 - 1;
        const bool valid = ((unsigned)iy < 128u) && ((unsigned)ix < 128u);
        const uint32_t vs = valid ? 16u : 0u;
        const int cy = valid ? iy : 0, cx = valid ? ix : 0;
        const size_t apix = ((size_t)(((ab << 7) + cy) << 7) + cx) * CIN + kc + lseg * 16;
        const uint32_t adst = sb + (uint32_t)stg * STAGE_BYTES + lrow * LDS_STRIDE_B + lseg * 32;
        cp_async16z(adst,                 g_Ahi + apix,     vs);
        cp_async16z(adst + 16,            g_Ahi + apix + 8, vs);
        cp_async16z(adst + OFF_ALO,       g_Alo + apix,     vs);
        cp_async16z(adst + OFF_ALO + 16,  g_Alo + apix + 8, vs);
        const size_t boff = (size_t)bgn * K_TOTAL + (size_t)tap * 128 + kc + lseg * 16;
        const uint32_t bdst = sb + (uint32_t)stg * STAGE_BYTES + OFF_BHI +
                              lrow * LDS_STRIDE_B + lseg * 32;
        cp_async16(bdst,                            g_Whi + boff);
        cp_async16(bdst + 16,                       g_Whi + boff + 8);
        cp_async16(bdst + (OFF_BLO - OFF_BHI),      g_Wlo + boff);
        cp_async16(bdst + (OFF_BLO - OFF_BHI) + 16, g_Wlo + boff + 8);
    };

    float acc[2][8][4];
    #pragma unroll
    for (int i = 0; i < 2; ++i)
        #pragma unroll
        for (int j = 0; j < 8; ++j)
            #pragma unroll
            for (int q = 0; q < 4; ++q) acc[i][j][q] = 0.f;

    // prologue
    issue_chunk(0, 0);
    cp_commit();

    #pragma unroll 1
    for (int c = 0; c < NCHUNK; ++c) {
        const int st = c & 1;

        cp_wait_all();
        __syncthreads();

        if (c + 1 < NCHUNK) {
            issue_chunk(c + 1, (c + 1) & 1);
            cp_commit();
        }

        // ---- compute chunk c from stage st ----
        const uint32_t a_s = sb + st * STAGE_BYTES;
        #pragma unroll
        for (int k16 = 0; k16 < 2; ++k16) {
            const int kb = k16 * 16;
            uint32_t ahi[2][4], alo[2][4];
            #pragma unroll
            for (int mt = 0; mt < 2; ++mt) {
                const int arow = wm * 32 + mt * 16 + (l & 15);
                const int acol = kb + (l >> 4) * 8;
                const uint32_t aaddr = a_s + arow * LDS_STRIDE_B + acol * 2;
                ldsm_x4(ahi[mt][0], ahi[mt][1], ahi[mt][2], ahi[mt][3], aaddr);
                ldsm_x4(alo[mt][0], alo[mt][1], alo[mt][2], alo[mt][3], aaddr + OFF_ALO);
            }
            #pragma unroll
            for (int np = 0; np < 4; ++np) {
                const int brow = wn * 64 + np * 16 + ((l >> 4) << 3) + (l & 7);
                const int bcol = kb + ((l >> 3) & 1) * 8;
                const uint32_t baddr = a_s + OFF_BHI + brow * LDS_STRIDE_B + bcol * 2;
                uint32_t bh[4], bl[4];
                ldsm_x4(bh[0], bh[1], bh[2], bh[3], baddr);
                ldsm_x4(bl[0], bl[1], bl[2], bl[3], baddr + (OFF_BLO - OFF_BHI));
                #pragma unroll
                for (int mt = 0; mt < 2; ++mt) {
                    #pragma unroll
                    for (int sub = 0; sub < 2; ++sub) {
                        float* a4 = acc[mt][np * 2 + sub];
                        mma16816(a4, ahi[mt], bh[sub * 2], bh[sub * 2 + 1]);
                        mma16816(a4, ahi[mt], bl[sub * 2], bl[sub * 2 + 1]);
                        mma16816(a4, alo[mt], bh[sub * 2], bh[sub * 2 + 1]);
                    }
                }
            }
        }
    }

    // ---- epilogue ----
    const int row_base = mblk * 128 + wm * 32 + (l >> 2);
    const int col_base = nblk * 128 + wn * 64 + (l & 3) * 2;
    #pragma unroll
    for (int mt = 0; mt < 2; ++mt) {
        #pragma unroll
        for (int nt = 0; nt < 8; ++nt) {
            const int r0 = row_base + mt * 16;
            const int cc = col_base + nt * 8;
            float* o0 = out + (size_t)r0 * COUT + cc;
            float* o1 = out + (size_t)(r0 + 8) * COUT + cc;
            *reinterpret_cast<float2*>(o0) = make_float2(acc[mt][nt][0], acc[mt][nt][1]);
            *reinterpret_cast<float2*>(o1) = make_float2(acc[mt][nt][2], acc[mt][nt][3]);
        }
    }
}

// ---------------- launch ----------------
extern "C" void kernel_launch(void* const* d_in, const int* in_sizes, int n_in,
                              void* d_out, int out_size)
{
    const float* feats  = (const float*)d_in[0];
    const float* weight = (const float*)d_in[1];
    const float* alpha  = (const float*)d_in[2];
    float* out = (float*)d_out;

    cudaFuncSetAttribute(conv_mma_kernel,
                         cudaFuncAttributeMaxDynamicSharedMemorySize, SMEM_TOTAL);

    wconv_kernel<<<(K_TOTAL * COUT + 255) / 256, 256>>>(weight);
    asplit_kernel<<<(NPIX * CIN / 4 + 255) / 256, 256>>>(feats);
    dim3 grid(M_TOTAL / BM, COUT / BN);   // (256, 2)
    conv_mma_kernel<<<grid, NTHREADS, SMEM_TOTAL>>>(alpha, out);
}